// round 11
// baseline (speedup 1.0000x reference)
#include <cuda_runtime.h>
#include <cuda_bf16.h>
#include <math.h>
#include <stdint.h>

#define BB      16
#define NVV     128
#define FDD     8192
#define ROWS_TOT (BB*NVV)          // 2048 rows per tensor
#define KSPLIT  8
#define KCHUNK  (FDD/KSPLIT)       // 1024
#define SLAB    32                 // k-columns per iteration
#define NITER   (KCHUNK/SLAB)      // 32
#define NSTG    2                  // cp.async fp32 stages (double buffer)
#define NTHR    512                // 16 warps, 4x4 warp grid

// SMEM layout (dynamic):
//   fp32 stages : 2 x 3 ops x 16384 B (128 rows x 32 fp32, swizzled 16B chunks)
//   bf16 tiles  : 2 x 3 ops x 16384 B (double-buffered, parity = iteration&1)
//   stats       : 5 x 512 floats
#define F32OP    16384
#define OFF_B16  (NSTG*3*F32OP)            // 98304
#define OFF_STAT (OFF_B16 + 2*3*16384)     // 196608
#define SMEM_TOT (OFF_STAT + 5*NTHR*4)     // 206848

#define EPSF    1e-6f
#define CONSTE  (8192.0f*1e-6f*1e-6f)
#define TINV    5.0f
#define MARGINF 1.0f

// ---------------- device scratch (static; no runtime allocation) --------
__device__ float g_Sp[(size_t)KSPLIT*BB*NVV*NVV];      // 8 MB  q.k^T partials
__device__ float g_Lp[(size_t)KSPLIT*BB*NVV*NVV];      // 8 MB  q.n^T partials
__device__ float g_ssp[3*KSPLIT*ROWS_TOT];             // per-chunk sum(x^2) q,k,n
__device__ float g_sup[2*KSPLIT*ROWS_TOT];             // per-chunk sum(x)   q,k
__device__ float g_parts2[BB*16*4];                    // per (batch,chunk) raw sums
__device__ unsigned int g_done = 0;                    // epi completion counter

// ---------------- PTX helpers (plain-sm_103-safe only) -------------------
__device__ __forceinline__ uint32_t s2u(const void* p) {
    uint32_t a;
    asm("{ .reg .u64 t; cvta.to.shared.u64 t, %1; cvt.u32.u64 %0, t; }"
        : "=r"(a) : "l"(p));
    return a;
}
#define CPA16(smem_u32, gptr) \
    asm volatile("cp.async.cg.shared.global [%0], [%1], 16;" \
                 :: "r"(smem_u32), "l"(gptr) : "memory")
#define CPA_COMMIT() asm volatile("cp.async.commit_group;" ::: "memory")
#define CPA_WAIT(n)  asm volatile("cp.async.wait_group %0;" :: "n"(n) : "memory")

// swizzle: 16B chunk c of row r placed at chunk (c ^ (r&7)); 128-B rows
__device__ __forceinline__ uint32_t tile_off(int row, int c) {
    return (uint32_t)(row * 128 + ((c ^ (row & 7)) << 4));
}

#define LDMX4(r0, r1, r2, r3, addr) \
    asm volatile("ldmatrix.sync.aligned.m8n8.x4.shared.b16 {%0,%1,%2,%3}, [%4];" \
        : "=r"(r0), "=r"(r1), "=r"(r2), "=r"(r3) : "r"(addr))

#define MMA16816(d, a, b0, b1) \
    asm volatile("mma.sync.aligned.m16n8k16.row.col.f32.bf16.bf16.f32 " \
        "{%0,%1,%2,%3}, {%4,%5,%6,%7}, {%8,%9}, {%0,%1,%2,%3};" \
        : "+f"((d)[0]), "+f"((d)[1]), "+f"((d)[2]), "+f"((d)[3]) \
        : "r"((a)[0]), "r"((a)[1]), "r"((a)[2]), "r"((a)[3]), "r"(b0), "r"(b1))

// convert 8 fp32 -> uint4 of bf16, accumulating stats
__device__ __forceinline__ uint4 cvt8(const float4 v0, const float4 v1,
                                      float& ss, float& su) {
    ss += v0.x*v0.x + v0.y*v0.y + v0.z*v0.z + v0.w*v0.w
        + v1.x*v1.x + v1.y*v1.y + v1.z*v1.z + v1.w*v1.w;
    su += v0.x + v0.y + v0.z + v0.w + v1.x + v1.y + v1.z + v1.w;
    union { __nv_bfloat162 h[4]; uint4 u; } pk;
    pk.h[0] = __float22bfloat162_rn(make_float2(v0.x, v0.y));
    pk.h[1] = __float22bfloat162_rn(make_float2(v0.z, v0.w));
    pk.h[2] = __float22bfloat162_rn(make_float2(v1.x, v1.y));
    pk.h[3] = __float22bfloat162_rn(make_float2(v1.z, v1.w));
    return pk.u;
}

// ---------------- kernel 1: FUSED stats + convert + dual bf16 GEMM --------
// grid (KSPLIT, BB), 512 threads (16 warps as 4x4; warptile 32M x 32N,
// two outputs S and L sharing A fragments). Reads fp32 q,k,n exactly once.
__device__ __forceinline__ void stage_load(uint32_t dst_stage,
                                           const float* q, const float* kk_,
                                           const float* nn_, int rowbase,
                                           int kelem, int tid) {
    #pragma unroll
    for (int h = 0; h < 6; h++) {
        int g = h * NTHR + tid;            // 0..3071 16B chunks
        int o = g >> 10;                   // op: 0=q 1=k 2=n
        int idx = g & 1023;
        int r = idx >> 3;
        int c = idx & 7;
        const float* src = (o == 0 ? q : (o == 1 ? kk_ : nn_))
                           + (size_t)(rowbase + r) * FDD + kelem + c * 4;
        CPA16(dst_stage + o * F32OP + tile_off(r, c), src);
    }
}

__global__ __launch_bounds__(NTHR, 1) void fused_k(const float* __restrict__ q,
                                                   const float* __restrict__ kk_,
                                                   const float* __restrict__ nn_) {
    extern __shared__ char smem[];
    int tid = threadIdx.x, wid = tid >> 5, lane = tid & 31;
    int wm = wid & 3, wn = wid >> 2;       // 4 x 4 warp grid
    int kc = blockIdx.x, b = blockIdx.y;
    int rowbase = b * NVV;
    int k0 = kc * KCHUNK;

    uint32_t sbase = s2u(smem);

    float accS[2][4][4], accL[2][4][4];
    #pragma unroll
    for (int mi = 0; mi < 2; mi++)
        #pragma unroll
        for (int ni = 0; ni < 4; ni++)
            #pragma unroll
            for (int e = 0; e < 4; e++) { accS[mi][ni][e] = 0.f; accL[mi][ni][e] = 0.f; }

    // stats: this thread owns row (tid&127), col-quarter (tid>>7)
    int crow = tid & 127, cq = tid >> 7;
    float ssq = 0.f, suq = 0.f, ssk = 0.f, suk = 0.f, ssn = 0.f;

    // ldmatrix lane geometry
    int a_row = wm * 32 + (lane & 15);                       // + mi*16
    int a_chi = (lane >> 4);                                 // + kk*2
    int b_row = wn * 32 + (lane & 7) + ((lane & 16) ? 8 : 0);// + nh*16
    int b_chi = (lane >> 3) & 1;                             // + kk*2

    // convert stage s (fp32 buf s&1) -> bf16 tiles (buf s&1), accumulate stats
    auto convert_stage = [&](int s) {
        const char* fbase = smem + (s & 1) * (3 * F32OP);
        char* bbase = smem + OFF_B16 + (s & 1) * (3 * F32OP);
        #pragma unroll
        for (int o = 0; o < 3; o++) {
            const char* f32 = fbase + o * F32OP;
            char* b16 = bbase + o * F32OP;
            float dss = 0.f, dsu = 0.f;
            float4 va = *(const float4*)(f32 + tile_off(crow, cq * 2));
            float4 vb = *(const float4*)(f32 + tile_off(crow, cq * 2 + 1));
            *(uint4*)(b16 + tile_off(crow, cq)) = cvt8(va, vb, dss, dsu);
            if (o == 0)      { ssq += dss; suq += dsu; }
            else if (o == 1) { ssk += dss; suk += dsu; }
            else             { ssn += dss; }
        }
    };

    // prologue: stage 0 and 1 in flight; convert stage 0
    stage_load(sbase + 0 * (3 * F32OP), q, kk_, nn_, rowbase, k0, tid);
    CPA_COMMIT();
    stage_load(sbase + 1 * (3 * F32OP), q, kk_, nn_, rowbase, k0 + SLAB, tid);
    CPA_COMMIT();
    CPA_WAIT(1);                           // stage 0 complete
    __syncthreads();
    convert_stage(0);
    __syncthreads();

    for (int it = 0; it < NITER; it++) {
        // prefetch stage it+2 into fp32 buf it&1 (its old contents converted)
        int pf = it + 2;
        if (pf < NITER)
            stage_load(sbase + (pf & 1) * (3 * F32OP), q, kk_, nn_,
                       rowbase, k0 + pf * SLAB, tid);
        CPA_COMMIT();
        CPA_WAIT(1);                       // stage it+1 complete
        __syncthreads();

        // overlapped region: convert(it+1) -> bf buf (it+1)&1,
        // MMA(it) reads bf buf it&1
        if (it + 1 < NITER) convert_stage(it + 1);

        uint32_t bb = sbase + OFF_B16 + (uint32_t)(it & 1) * (3 * F32OP);
        uint32_t smA  = bb;
        uint32_t smBk = bb + F32OP;
        uint32_t smBn = bb + 2 * F32OP;
        #pragma unroll
        for (int kk = 0; kk < 2; kk++) {   // K=32 -> two K=16 steps
            uint32_t af[2][4];
            #pragma unroll
            for (int mi = 0; mi < 2; mi++)
                LDMX4(af[mi][0], af[mi][1], af[mi][2], af[mi][3],
                      smA + tile_off(a_row + mi * 16, kk * 2 + a_chi));
            uint32_t bk[2][4], bn[2][4];
            #pragma unroll
            for (int nh = 0; nh < 2; nh++) {
                LDMX4(bk[nh][0], bk[nh][1], bk[nh][2], bk[nh][3],
                      smBk + tile_off(b_row + nh * 16, kk * 2 + b_chi));
                LDMX4(bn[nh][0], bn[nh][1], bn[nh][2], bn[nh][3],
                      smBn + tile_off(b_row + nh * 16, kk * 2 + b_chi));
            }
            #pragma unroll
            for (int mi = 0; mi < 2; mi++)
                #pragma unroll
                for (int ni = 0; ni < 4; ni++) {
                    MMA16816(accS[mi][ni], af[mi],
                             bk[ni >> 1][(ni & 1) * 2], bk[ni >> 1][(ni & 1) * 2 + 1]);
                    MMA16816(accL[mi][ni], af[mi],
                             bn[ni >> 1][(ni & 1) * 2], bn[ni >> 1][(ni & 1) * 2 + 1]);
                }
        }
        __syncthreads();                   // bf(it+1) complete; fp32 buf reusable
    }

    // ---- stats write-out: combine the four col-quarters of each row ----
    {
        float* st = (float*)(smem + OFF_STAT);
        st[0 * NTHR + tid] = ssq;
        st[1 * NTHR + tid] = suq;
        st[2 * NTHR + tid] = ssk;
        st[3 * NTHR + tid] = suk;
        st[4 * NTHR + tid] = ssn;
        __syncthreads();
        if (tid < 128) {
            int gr = rowbase + tid;
            float a0 = 0.f, a1 = 0.f, a2 = 0.f, a3 = 0.f, a4 = 0.f;
            #pragma unroll
            for (int j = 0; j < 4; j++) {
                a0 += st[0 * NTHR + tid + 128 * j];
                a1 += st[1 * NTHR + tid + 128 * j];
                a2 += st[2 * NTHR + tid + 128 * j];
                a3 += st[3 * NTHR + tid + 128 * j];
                a4 += st[4 * NTHR + tid + 128 * j];
            }
            g_ssp[(0 * KSPLIT + kc) * ROWS_TOT + gr] = a0;
            g_sup[(0 * KSPLIT + kc) * ROWS_TOT + gr] = a1;
            g_ssp[(1 * KSPLIT + kc) * ROWS_TOT + gr] = a2;
            g_sup[(1 * KSPLIT + kc) * ROWS_TOT + gr] = a3;
            g_ssp[(2 * KSPLIT + kc) * ROWS_TOT + gr] = a4;
        }
    }

    // ---- GEMM epilogue: write fp32 partials for both outputs ----
    float* outS = g_Sp + ((size_t)kc * BB + b) * (NVV * NVV);
    float* outL = g_Lp + ((size_t)kc * BB + b) * (NVV * NVV);
    int gr2 = lane >> 2, tc = lane & 3;
    #pragma unroll
    for (int mi = 0; mi < 2; mi++) {
        #pragma unroll
        for (int ni = 0; ni < 4; ni++) {
            int r0 = wm * 32 + mi * 16 + gr2;
            int col = wn * 32 + ni * 8 + tc * 2;
            *(float2*)&outS[(size_t)r0 * NVV + col] =
                make_float2(accS[mi][ni][0], accS[mi][ni][1]);
            *(float2*)&outS[(size_t)(r0 + 8) * NVV + col] =
                make_float2(accS[mi][ni][2], accS[mi][ni][3]);
            *(float2*)&outL[(size_t)r0 * NVV + col] =
                make_float2(accL[mi][ni][0], accL[mi][ni][1]);
            *(float2*)&outL[(size_t)(r0 + 8) * NVV + col] =
                make_float2(accL[mi][ni][2], accL[mi][ni][3]);
        }
    }
}

// ---------------- kernel 2: stats-reduce + normalize + loss + final ------
// grid (16, BB). The LAST CTA (threadfence+counter) also does the final
// weighted combine (fixed-order, deterministic) and writes the output.
__global__ __launch_bounds__(256) void epi3_k(float* out, int out_size) {
    int chunk = blockIdx.x, b = blockIdx.y, tid = threadIdx.x;
    __shared__ float invq[NVV], invk[NVV], invn[NVV];
    __shared__ float sqv[NVV], skv[NVV], dqk_d[NVV], dkq_d[NVV], sdiag[NVV];

    if (tid < NVV) {
        int gr = b * NVV + tid;
        float ssq = 0.f, ssk = 0.f, ssn = 0.f, suq = 0.f, suk = 0.f;
        #pragma unroll
        for (int p = 0; p < KSPLIT; p++) {
            ssq += g_ssp[(0 * KSPLIT + p) * ROWS_TOT + gr];
            ssk += g_ssp[(1 * KSPLIT + p) * ROWS_TOT + gr];
            ssn += g_ssp[(2 * KSPLIT + p) * ROWS_TOT + gr];
            suq += g_sup[(0 * KSPLIT + p) * ROWS_TOT + gr];
            suk += g_sup[(1 * KSPLIT + p) * ROWS_TOT + gr];
        }
        float iq = 1.f / fmaxf(sqrtf(ssq), 1e-12f);
        float ik = 1.f / fmaxf(sqrtf(ssk), 1e-12f);
        invq[tid] = iq; invk[tid] = ik;
        invn[tid] = 1.f / fmaxf(sqrtf(ssn), 1e-12f);
        float sq = suq * iq, sk = suk * ik;
        sqv[tid] = sq; skv[tid] = sk;
        float sr = 0.f;
        #pragma unroll
        for (int p = 0; p < KSPLIT; p++)
            sr += g_Sp[(size_t)(p * BB + b) * (NVV * NVV) + tid * (NVV + 1)];
        float Sii = sr * iq * ik;
        sdiag[tid] = Sii;
        dqk_d[tid] = sqrtf(fmaxf(2.f - 2.f * Sii + 2.f * EPSF * (sq - sk) + CONSTE, 0.f));
        dkq_d[tid] = sqrtf(fmaxf(2.f - 2.f * Sii + 2.f * EPSF * (sk - sq) + CONSTE, 0.f));
    }
    __syncthreads();

    const float* Sp0 = g_Sp + (size_t)b * (NVV * NVV);
    const float* Lp0 = g_Lp + (size_t)b * (NVV * NVV);
    const size_t PST = (size_t)BB * NVV * NVV;     // stride between K-split slabs

    float smacc = 0.f, triacc = 0.f, cycacc = 0.f, ceacc = 0.f;
    #pragma unroll
    for (int h = 0; h < 4; h++) {
        int idx = h * 256 + tid;           // 0..1023 over 8 rows x 128 cols
        int il = idx >> 7, j = idx & 127;
        int i = chunk * 8 + il;
        float sr = 0.f;
        #pragma unroll
        for (int p = 0; p < KSPLIT; p++) sr += Sp0[p * PST + i * NVV + j];
        float Sij = sr * invq[i] * invk[j];
        if (i == j) {
            float d = Sij - 1.f; smacc += d * d;
        } else {
            smacc += Sij * Sij;
            float st = 0.f;
            #pragma unroll
            for (int p = 0; p < KSPLIT; p++) st += Sp0[p * PST + j * NVV + i];
            float Sji = st * invq[j] * invk[i];
            cycacc += fabsf(Sij - Sji);
            float dq = sqrtf(fmaxf(2.f - 2.f * Sij + 2.f * EPSF * (sqv[i] - skv[j]) + CONSTE, 0.f));
            triacc += fmaxf(dqk_d[i] - dq + MARGINF, 0.f);
            float dk = sqrtf(fmaxf(2.f - 2.f * Sij + 2.f * EPSF * (skv[j] - sqv[i]) + CONSTE, 0.f));
            triacc += fmaxf(dkq_d[j] - dk + MARGINF, 0.f);
        }
    }

    // InfoNCE: warp w handles row chunk*8 + w (129 logits)
    int lane = tid & 31, w = tid >> 5;
    {
        int i = chunk * 8 + w;
        float iq = invq[i];
        float lpos = sdiag[i] * TINV;
        float mx = lpos;
        float lg[4];
        #pragma unroll
        for (int m = 0; m < 4; m++) {
            int j = lane + m * 32;
            float lr = 0.f;
            #pragma unroll
            for (int p = 0; p < KSPLIT; p++) lr += Lp0[p * PST + i * NVV + j];
            lg[m] = lr * iq * invn[j] * TINV;
            mx = fmaxf(mx, lg[m]);
        }
        #pragma unroll
        for (int o = 16; o > 0; o >>= 1) mx = fmaxf(mx, __shfl_xor_sync(0xffffffffu, mx, o));
        float se = (lane == 0) ? expf(lpos - mx) : 0.f;
        #pragma unroll
        for (int m = 0; m < 4; m++) se += expf(lg[m] - mx);
        #pragma unroll
        for (int o = 16; o > 0; o >>= 1) se += __shfl_xor_sync(0xffffffffu, se, o);
        if (lane == 0) ceacc = mx + logf(se) - lpos;
    }

    __shared__ float red[4][8];
    #pragma unroll
    for (int o = 16; o > 0; o >>= 1) {
        smacc  += __shfl_xor_sync(0xffffffffu, smacc,  o);
        triacc += __shfl_xor_sync(0xffffffffu, triacc, o);
        cycacc += __shfl_xor_sync(0xffffffffu, cycacc, o);
        ceacc  += __shfl_xor_sync(0xffffffffu, ceacc,  o);
    }
    if (lane == 0) { red[0][w] = smacc; red[1][w] = triacc; red[2][w] = cycacc; red[3][w] = ceacc; }
    __syncthreads();
    if (tid == 0) {
        float a = 0.f, t = 0.f, c = 0.f, e = 0.f;
        #pragma unroll
        for (int i = 0; i < 8; i++) { a += red[0][i]; t += red[1][i]; c += red[2][i]; e += red[3][i]; }
        float* p = &g_parts2[(b * 16 + chunk) * 4];
        p[0] = a; p[1] = t; p[2] = c; p[3] = e;
    }

    // ---- last-CTA final combine (threadfence reduction pattern) ----
    __shared__ unsigned int s_isLast;
    __threadfence();
    if (tid == 0) {
        unsigned int prev = atomicAdd(&g_done, 1u);
        s_isLast = (prev == (16u * BB - 1u)) ? 1u : 0u;
    }
    __syncthreads();
    if (s_isLast) {
        float acc = 0.f;
        #pragma unroll
        for (int h = 0; h < 4; h++) {
            int e = h * 256 + tid;         // 0..1023 over (b, chunk, comp)
            int bb2 = e >> 6;
            int comp = e & 3;
            float p = __ldcg(&g_parts2[e]);
            float wgt;
            if (comp == 1)      wgt = (float)(BB - bb2) / (float)(2 * NVV * (NVV - 1));
            else if (comp == 2) wgt = 1.f / (float)(NVV * (NVV - 1));
            else                wgt = 1.f / (float)(NVV * NVV);
            acc += wgt * p;
        }
        __shared__ float fred[8];
        #pragma unroll
        for (int o = 16; o > 0; o >>= 1) acc += __shfl_xor_sync(0xffffffffu, acc, o);
        if (lane == 0) fred[w] = acc;
        __syncthreads();
        __shared__ float s_ssl;
        if (tid == 0) {
            float t = 0.f;
            #pragma unroll
            for (int i = 0; i < 8; i++) t += fred[i];
            s_ssl = t;
            g_done = 0;                    // reset for next graph replay
        }
        __syncthreads();
        float v = s_ssl;
        for (int i = tid; i < out_size; i += 256) out[i] = v;
    }
}

// ---------------- launch -----------------------------------------------
extern "C" void kernel_launch(void* const* d_in, const int* in_sizes, int n_in,
                              void* d_out, int out_size) {
    const float* q = (const float*)d_in[0];
    const float* k = (const float*)d_in[1];
    const float* n = (const float*)d_in[2];
    // d_in[3] = num_gt; fixed at 128 == NV for these shapes.

    cudaFuncSetAttribute(fused_k, cudaFuncAttributeMaxDynamicSharedMemorySize, SMEM_TOT);

    dim3 gg(KSPLIT, BB);
    fused_k<<<gg, NTHR, SMEM_TOT>>>(q, k, n);
    dim3 ge(16, BB);
    epi3_k<<<ge, 256>>>((float*)d_out, out_size);
}

// round 13
// speedup vs baseline: 1.0962x; 1.0962x over previous
#include <cuda_runtime.h>
#include <cuda_bf16.h>
#include <math.h>
#include <stdint.h>

#define BB      16
#define NVV     128
#define FDD     8192
#define ROWS_TOT (BB*NVV)          // 2048 rows per tensor
#define KSPLIT  8
#define KCHUNK  (FDD/KSPLIT)       // 1024
#define SLAB    32                 // k-columns per iteration
#define NITER   (KCHUNK/SLAB)      // 32
#define NSTG    2                  // cp.async fp32 stages (double buffer)
#define NTHR    512                // 16 warps, 4x4 warp grid

#define F32OP    16384
#define OFF_B16  (NSTG*3*F32OP)            // 98304
#define OFF_STAT (OFF_B16 + 2*3*16384)     // 196608
#define SMEM_TOT (OFF_STAT + 5*NTHR*4)     // 206848

#define EPSF    1e-6f
#define CONSTE  (8192.0f*1e-6f*1e-6f)
#define TINV    5.0f
#define MARGINF 1.0f

// ---------------- device scratch (static; no runtime allocation) --------
__device__ float g_Sp[(size_t)KSPLIT*BB*NVV*NVV];      // 8 MB  q.k^T partials
__device__ float g_Lp[(size_t)KSPLIT*BB*NVV*NVV];      // 8 MB  q.n^T partials
__device__ float g_S[(size_t)BB*NVV*NVV];              // 1 MB  collapsed raw S
__device__ float g_L[(size_t)BB*NVV*NVV];              // 1 MB  collapsed raw L
__device__ float g_ssp[3*KSPLIT*ROWS_TOT];             // per-chunk sum(x^2) q,k,n
__device__ float g_sup[2*KSPLIT*ROWS_TOT];             // per-chunk sum(x)   q,k
__device__ float g_parts2[BB*16*4];                    // per (batch,chunk) raw sums
__device__ unsigned int g_done = 0;                    // epi completion counter

// ---------------- PTX helpers (plain-sm_103-safe only) -------------------
__device__ __forceinline__ uint32_t s2u(const void* p) {
    uint32_t a;
    asm("{ .reg .u64 t; cvta.to.shared.u64 t, %1; cvt.u32.u64 %0, t; }"
        : "=r"(a) : "l"(p));
    return a;
}
#define CPA16(smem_u32, gptr) \
    asm volatile("cp.async.cg.shared.global [%0], [%1], 16;" \
                 :: "r"(smem_u32), "l"(gptr) : "memory")
#define CPA_COMMIT() asm volatile("cp.async.commit_group;" ::: "memory")
#define CPA_WAIT(n)  asm volatile("cp.async.wait_group %0;" :: "n"(n) : "memory")

__device__ __forceinline__ uint32_t tile_off(int row, int c) {
    return (uint32_t)(row * 128 + ((c ^ (row & 7)) << 4));
}

#define LDMX4(r0, r1, r2, r3, addr) \
    asm volatile("ldmatrix.sync.aligned.m8n8.x4.shared.b16 {%0,%1,%2,%3}, [%4];" \
        : "=r"(r0), "=r"(r1), "=r"(r2), "=r"(r3) : "r"(addr))

#define MMA16816(d, a, b0, b1) \
    asm volatile("mma.sync.aligned.m16n8k16.row.col.f32.bf16.bf16.f32 " \
        "{%0,%1,%2,%3}, {%4,%5,%6,%7}, {%8,%9}, {%0,%1,%2,%3};" \
        : "+f"((d)[0]), "+f"((d)[1]), "+f"((d)[2]), "+f"((d)[3]) \
        : "r"((a)[0]), "r"((a)[1]), "r"((a)[2]), "r"((a)[3]), "r"(b0), "r"(b1))

__device__ __forceinline__ uint4 cvt8(const float4 v0, const float4 v1,
                                      float& ss, float& su) {
    ss += v0.x*v0.x + v0.y*v0.y + v0.z*v0.z + v0.w*v0.w
        + v1.x*v1.x + v1.y*v1.y + v1.z*v1.z + v1.w*v1.w;
    su += v0.x + v0.y + v0.z + v0.w + v1.x + v1.y + v1.z + v1.w;
    union { __nv_bfloat162 h[4]; uint4 u; } pk;
    pk.h[0] = __float22bfloat162_rn(make_float2(v0.x, v0.y));
    pk.h[1] = __float22bfloat162_rn(make_float2(v0.z, v0.w));
    pk.h[2] = __float22bfloat162_rn(make_float2(v1.x, v1.y));
    pk.h[3] = __float22bfloat162_rn(make_float2(v1.z, v1.w));
    return pk.u;
}

// ---------------- kernel 1: FUSED stats + convert + dual bf16 GEMM --------
// (unchanged from round 11) grid (KSPLIT, BB), 512 threads, 4x4 warp grid.
__device__ __forceinline__ void stage_load(uint32_t dst_stage,
                                           const float* q, const float* kk_,
                                           const float* nn_, int rowbase,
                                           int kelem, int tid) {
    #pragma unroll
    for (int h = 0; h < 6; h++) {
        int g = h * NTHR + tid;            // 0..3071 16B chunks
        int o = g >> 10;                   // op: 0=q 1=k 2=n
        int idx = g & 1023;
        int r = idx >> 3;
        int c = idx & 7;
        const float* src = (o == 0 ? q : (o == 1 ? kk_ : nn_))
                           + (size_t)(rowbase + r) * FDD + kelem + c * 4;
        CPA16(dst_stage + o * F32OP + tile_off(r, c), src);
    }
}

__global__ __launch_bounds__(NTHR, 1) void fused_k(const float* __restrict__ q,
                                                   const float* __restrict__ kk_,
                                                   const float* __restrict__ nn_) {
    extern __shared__ char smem[];
    int tid = threadIdx.x, wid = tid >> 5, lane = tid & 31;
    int wm = wid & 3, wn = wid >> 2;       // 4 x 4 warp grid
    int kc = blockIdx.x, b = blockIdx.y;
    int rowbase = b * NVV;
    int k0 = kc * KCHUNK;

    uint32_t sbase = s2u(smem);

    float accS[2][4][4], accL[2][4][4];
    #pragma unroll
    for (int mi = 0; mi < 2; mi++)
        #pragma unroll
        for (int ni = 0; ni < 4; ni++)
            #pragma unroll
            for (int e = 0; e < 4; e++) { accS[mi][ni][e] = 0.f; accL[mi][ni][e] = 0.f; }

    int crow = tid & 127, cq = tid >> 7;
    float ssq = 0.f, suq = 0.f, ssk = 0.f, suk = 0.f, ssn = 0.f;

    int a_row = wm * 32 + (lane & 15);
    int a_chi = (lane >> 4);
    int b_row = wn * 32 + (lane & 7) + ((lane & 16) ? 8 : 0);
    int b_chi = (lane >> 3) & 1;

    auto convert_stage = [&](int s) {
        const char* fbase = smem + (s & 1) * (3 * F32OP);
        char* bbase = smem + OFF_B16 + (s & 1) * (3 * F32OP);
        #pragma unroll
        for (int o = 0; o < 3; o++) {
            const char* f32 = fbase + o * F32OP;
            char* b16 = bbase + o * F32OP;
            float dss = 0.f, dsu = 0.f;
            float4 va = *(const float4*)(f32 + tile_off(crow, cq * 2));
            float4 vb = *(const float4*)(f32 + tile_off(crow, cq * 2 + 1));
            *(uint4*)(b16 + tile_off(crow, cq)) = cvt8(va, vb, dss, dsu);
            if (o == 0)      { ssq += dss; suq += dsu; }
            else if (o == 1) { ssk += dss; suk += dsu; }
            else             { ssn += dss; }
        }
    };

    stage_load(sbase + 0 * (3 * F32OP), q, kk_, nn_, rowbase, k0, tid);
    CPA_COMMIT();
    stage_load(sbase + 1 * (3 * F32OP), q, kk_, nn_, rowbase, k0 + SLAB, tid);
    CPA_COMMIT();
    CPA_WAIT(1);
    __syncthreads();
    convert_stage(0);
    __syncthreads();

    for (int it = 0; it < NITER; it++) {
        int pf = it + 2;
        if (pf < NITER)
            stage_load(sbase + (pf & 1) * (3 * F32OP), q, kk_, nn_,
                       rowbase, k0 + pf * SLAB, tid);
        CPA_COMMIT();
        CPA_WAIT(1);
        __syncthreads();

        if (it + 1 < NITER) convert_stage(it + 1);

        uint32_t bb = sbase + OFF_B16 + (uint32_t)(it & 1) * (3 * F32OP);
        uint32_t smA  = bb;
        uint32_t smBk = bb + F32OP;
        uint32_t smBn = bb + 2 * F32OP;
        #pragma unroll
        for (int kk = 0; kk < 2; kk++) {
            uint32_t af[2][4];
            #pragma unroll
            for (int mi = 0; mi < 2; mi++)
                LDMX4(af[mi][0], af[mi][1], af[mi][2], af[mi][3],
                      smA + tile_off(a_row + mi * 16, kk * 2 + a_chi));
            uint32_t bk[2][4], bn[2][4];
            #pragma unroll
            for (int nh = 0; nh < 2; nh++) {
                LDMX4(bk[nh][0], bk[nh][1], bk[nh][2], bk[nh][3],
                      smBk + tile_off(b_row + nh * 16, kk * 2 + b_chi));
                LDMX4(bn[nh][0], bn[nh][1], bn[nh][2], bn[nh][3],
                      smBn + tile_off(b_row + nh * 16, kk * 2 + b_chi));
            }
            #pragma unroll
            for (int mi = 0; mi < 2; mi++)
                #pragma unroll
                for (int ni = 0; ni < 4; ni++) {
                    MMA16816(accS[mi][ni], af[mi],
                             bk[ni >> 1][(ni & 1) * 2], bk[ni >> 1][(ni & 1) * 2 + 1]);
                    MMA16816(accL[mi][ni], af[mi],
                             bn[ni >> 1][(ni & 1) * 2], bn[ni >> 1][(ni & 1) * 2 + 1]);
                }
        }
        __syncthreads();
    }

    {
        float* st = (float*)(smem + OFF_STAT);
        st[0 * NTHR + tid] = ssq;
        st[1 * NTHR + tid] = suq;
        st[2 * NTHR + tid] = ssk;
        st[3 * NTHR + tid] = suk;
        st[4 * NTHR + tid] = ssn;
        __syncthreads();
        if (tid < 128) {
            int gr = rowbase + tid;
            float a0 = 0.f, a1 = 0.f, a2 = 0.f, a3 = 0.f, a4 = 0.f;
            #pragma unroll
            for (int j = 0; j < 4; j++) {
                a0 += st[0 * NTHR + tid + 128 * j];
                a1 += st[1 * NTHR + tid + 128 * j];
                a2 += st[2 * NTHR + tid + 128 * j];
                a3 += st[3 * NTHR + tid + 128 * j];
                a4 += st[4 * NTHR + tid + 128 * j];
            }
            g_ssp[(0 * KSPLIT + kc) * ROWS_TOT + gr] = a0;
            g_sup[(0 * KSPLIT + kc) * ROWS_TOT + gr] = a1;
            g_ssp[(1 * KSPLIT + kc) * ROWS_TOT + gr] = a2;
            g_sup[(1 * KSPLIT + kc) * ROWS_TOT + gr] = a3;
            g_ssp[(2 * KSPLIT + kc) * ROWS_TOT + gr] = a4;
        }
    }

    float* outS = g_Sp + ((size_t)kc * BB + b) * (NVV * NVV);
    float* outL = g_Lp + ((size_t)kc * BB + b) * (NVV * NVV);
    int gr2 = lane >> 2, tc = lane & 3;
    #pragma unroll
    for (int mi = 0; mi < 2; mi++) {
        #pragma unroll
        for (int ni = 0; ni < 4; ni++) {
            int r0 = wm * 32 + mi * 16 + gr2;
            int col = wn * 32 + ni * 8 + tc * 2;
            *(float2*)&outS[(size_t)r0 * NVV + col] =
                make_float2(accS[mi][ni][0], accS[mi][ni][1]);
            *(float2*)&outS[(size_t)(r0 + 8) * NVV + col] =
                make_float2(accS[mi][ni][2], accS[mi][ni][3]);
            *(float2*)&outL[(size_t)r0 * NVV + col] =
                make_float2(accL[mi][ni][0], accL[mi][ni][1]);
            *(float2*)&outL[(size_t)(r0 + 8) * NVV + col] =
                make_float2(accL[mi][ni][2], accL[mi][ni][3]);
        }
    }
}

// ---------------- kernel 2: collapse K-split slabs (coalesced) -----------
// 2 matrices x 65536 float4; each thread sums 8 slabs for one float4.
#define TOT4 (BB*NVV*NVV/4)                // 65536
__global__ __launch_bounds__(256) void reduce_k() {
    int idx = blockIdx.x * 256 + threadIdx.x;      // 0 .. 2*TOT4-1
    int m = idx >> 17;                              // 0=S, 1=L (TOT4 = 1<<16; 2*TOT4 ids)
    int e4 = idx & (TOT4 - 1);
    const float4* src = (const float4*)(m ? g_Lp : g_Sp);
    float4 a = src[e4];
    #pragma unroll
    for (int p = 1; p < KSPLIT; p++) {
        float4 v = src[(size_t)p * TOT4 + e4];
        a.x += v.x; a.y += v.y; a.z += v.z; a.w += v.w;
    }
    ((float4*)(m ? g_L : g_S))[e4] = a;
}

// ---------------- kernel 3: normalize + loss epilogue + last-CTA final ---
// grid (16, BB): 8 rows of the 128x128 matrices per CTA; single-slab reads.
__global__ __launch_bounds__(256) void epi4_k(float* out, int out_size) {
    int chunk = blockIdx.x, b = blockIdx.y, tid = threadIdx.x;
    __shared__ float invq[NVV], invk[NVV], invn[NVV];
    __shared__ float sqv[NVV], skv[NVV], dqk_d[NVV], dkq_d[NVV], sdiag[NVV];

    const float* S = g_S + (size_t)b * (NVV * NVV);
    const float* L = g_L + (size_t)b * (NVV * NVV);

    if (tid < NVV) {
        int gr = b * NVV + tid;
        float ssq = 0.f, ssk = 0.f, ssn = 0.f, suq = 0.f, suk = 0.f;
        #pragma unroll
        for (int p = 0; p < KSPLIT; p++) {
            ssq += g_ssp[(0 * KSPLIT + p) * ROWS_TOT + gr];
            ssk += g_ssp[(1 * KSPLIT + p) * ROWS_TOT + gr];
            ssn += g_ssp[(2 * KSPLIT + p) * ROWS_TOT + gr];
            suq += g_sup[(0 * KSPLIT + p) * ROWS_TOT + gr];
            suk += g_sup[(1 * KSPLIT + p) * ROWS_TOT + gr];
        }
        float iq = 1.f / fmaxf(sqrtf(ssq), 1e-12f);
        float ik = 1.f / fmaxf(sqrtf(ssk), 1e-12f);
        invq[tid] = iq; invk[tid] = ik;
        invn[tid] = 1.f / fmaxf(sqrtf(ssn), 1e-12f);
        float sq = suq * iq, sk = suk * ik;
        sqv[tid] = sq; skv[tid] = sk;
        float Sii = S[tid * (NVV + 1)] * iq * ik;
        sdiag[tid] = Sii;
        dqk_d[tid] = sqrtf(fmaxf(2.f - 2.f * Sii + 2.f * EPSF * (sq - sk) + CONSTE, 0.f));
        dkq_d[tid] = sqrtf(fmaxf(2.f - 2.f * Sii + 2.f * EPSF * (sk - sq) + CONSTE, 0.f));
    }
    __syncthreads();

    float smacc = 0.f, triacc = 0.f, cycacc = 0.f, ceacc = 0.f;
    #pragma unroll
    for (int h = 0; h < 4; h++) {
        int idx = h * 256 + tid;           // 0..1023 over 8 rows x 128 cols
        int il = idx >> 7, j = idx & 127;
        int i = chunk * 8 + il;
        float Sij = S[i * NVV + j] * invq[i] * invk[j];
        if (i == j) {
            float d = Sij - 1.f; smacc += d * d;
        } else {
            smacc += Sij * Sij;
            float Sji = S[j * NVV + i] * invq[j] * invk[i];
            cycacc += fabsf(Sij - Sji);
            float dq = sqrtf(fmaxf(2.f - 2.f * Sij + 2.f * EPSF * (sqv[i] - skv[j]) + CONSTE, 0.f));
            triacc += fmaxf(dqk_d[i] - dq + MARGINF, 0.f);
            float dk = sqrtf(fmaxf(2.f - 2.f * Sij + 2.f * EPSF * (skv[j] - sqv[i]) + CONSTE, 0.f));
            triacc += fmaxf(dkq_d[j] - dk + MARGINF, 0.f);
        }
    }

    // InfoNCE: warp w handles row chunk*8 + w (129 logits)
    int lane = tid & 31, w = tid >> 5;
    {
        int i = chunk * 8 + w;
        float iq = invq[i];
        float lpos = sdiag[i] * TINV;
        float mx = lpos;
        float lg[4];
        #pragma unroll
        for (int m = 0; m < 4; m++) {
            int j = lane + m * 32;
            lg[m] = L[i * NVV + j] * iq * invn[j] * TINV;
            mx = fmaxf(mx, lg[m]);
        }
        #pragma unroll
        for (int o = 16; o > 0; o >>= 1) mx = fmaxf(mx, __shfl_xor_sync(0xffffffffu, mx, o));
        float se = (lane == 0) ? expf(lpos - mx) : 0.f;
        #pragma unroll
        for (int m = 0; m < 4; m++) se += expf(lg[m] - mx);
        #pragma unroll
        for (int o = 16; o > 0; o >>= 1) se += __shfl_xor_sync(0xffffffffu, se, o);
        if (lane == 0) ceacc = mx + logf(se) - lpos;
    }

    __shared__ float red[4][8];
    #pragma unroll
    for (int o = 16; o > 0; o >>= 1) {
        smacc  += __shfl_xor_sync(0xffffffffu, smacc,  o);
        triacc += __shfl_xor_sync(0xffffffffu, triacc, o);
        cycacc += __shfl_xor_sync(0xffffffffu, cycacc, o);
        ceacc  += __shfl_xor_sync(0xffffffffu, ceacc,  o);
    }
    if (lane == 0) { red[0][w] = smacc; red[1][w] = triacc; red[2][w] = cycacc; red[3][w] = ceacc; }
    __syncthreads();
    if (tid == 0) {
        float a = 0.f, t = 0.f, c = 0.f, e = 0.f;
        #pragma unroll
        for (int i = 0; i < 8; i++) { a += red[0][i]; t += red[1][i]; c += red[2][i]; e += red[3][i]; }
        float* p = &g_parts2[(b * 16 + chunk) * 4];
        p[0] = a; p[1] = t; p[2] = c; p[3] = e;
    }

    // ---- last-CTA final combine (threadfence reduction pattern) ----
    __shared__ unsigned int s_isLast;
    __threadfence();
    if (tid == 0) {
        unsigned int prev = atomicAdd(&g_done, 1u);
        s_isLast = (prev == (16u * BB - 1u)) ? 1u : 0u;
    }
    __syncthreads();
    if (s_isLast) {
        float acc = 0.f;
        #pragma unroll
        for (int h = 0; h < 4; h++) {
            int e = h * 256 + tid;         // 0..1023 over (b, chunk, comp)
            int bb2 = e >> 6;
            int comp = e & 3;
            float p = __ldcg(&g_parts2[e]);
            float wgt;
            if (comp == 1)      wgt = (float)(BB - bb2) / (float)(2 * NVV * (NVV - 1));
            else if (comp == 2) wgt = 1.f / (float)(NVV * (NVV - 1));
            else                wgt = 1.f / (float)(NVV * NVV);
            acc += wgt * p;
        }
        __shared__ float fred[8];
        #pragma unroll
        for (int o = 16; o > 0; o >>= 1) acc += __shfl_xor_sync(0xffffffffu, acc, o);
        if (lane == 0) fred[w] = acc;
        __syncthreads();
        __shared__ float s_ssl;
        if (tid == 0) {
            float t = 0.f;
            #pragma unroll
            for (int i = 0; i < 8; i++) t += fred[i];
            s_ssl = t;
            g_done = 0;                    // reset for next graph replay
        }
        __syncthreads();
        float v = s_ssl;
        for (int i = tid; i < out_size; i += 256) out[i] = v;
    }
}

// ---------------- launch -----------------------------------------------
extern "C" void kernel_launch(void* const* d_in, const int* in_sizes, int n_in,
                              void* d_out, int out_size) {
    const float* q = (const float*)d_in[0];
    const float* k = (const float*)d_in[1];
    const float* n = (const float*)d_in[2];
    // d_in[3] = num_gt; fixed at 128 == NV for these shapes.

    cudaFuncSetAttribute(fused_k, cudaFuncAttributeMaxDynamicSharedMemorySize, SMEM_TOT);

    dim3 gg(KSPLIT, BB);
    fused_k<<<gg, NTHR, SMEM_TOT>>>(q, k, n);
    reduce_k<<<(2 * TOT4) / 256, 256>>>();
    dim3 ge(16, BB);
    epi4_k<<<ge, 256>>>((float*)d_out, out_size);
}